// round 1
// baseline (speedup 1.0000x reference)
#include <cuda_runtime.h>
#include <cstdint>

#define D 128

// Flag: 1 if src/dst are int64, 0 if int32. Written by detect kernel each call.
__device__ int g_idx64;

__global__ void detect_idx_kernel(const void* __restrict__ src, long long n_nodes) {
    // Values are uniform in [0, n_nodes). If stored int32 but read as int64,
    // each word combines two indices -> value >= 2^32 with overwhelming
    // probability across 8 samples (fails only if all 8 high words are 0,
    // p ~ (1e-5)^8).
    const long long* s64 = (const long long*)src;
    bool ok = true;
#pragma unroll
    for (int i = 0; i < 8; i++) {
        long long v = s64[i];
        if (v < 0 || v >= n_nodes) ok = false;
    }
    g_idx64 = ok ? 1 : 0;
}

__global__ void zero_kernel(float4* __restrict__ out, int n4) {
    int i = blockIdx.x * blockDim.x + threadIdx.x;
    if (i < n4) out[i] = make_float4(0.f, 0.f, 0.f, 0.f);
}

__global__ __launch_bounds__(256)
void tp_scatter_kernel(const float* __restrict__ x,
                       const float* __restrict__ y,
                       const float* __restrict__ coeffs,
                       const void* __restrict__ srcp,
                       const void* __restrict__ dstp,
                       float* __restrict__ out,
                       int E)
{
    int gid = blockIdx.x * blockDim.x + threadIdx.x;
    int e = gid >> 5;
    if (e >= E) return;
    int lane = gid & 31;
    int col = lane << 2;                 // 0..124, 16B-aligned chunk

    long long s, d;
    if (g_idx64) {                        // uniform branch (same for all threads)
        s = ((const long long*)srcp)[e];
        d = ((const long long*)dstp)[e];
    } else {
        s = (long long)((const int*)srcp)[e];
        d = (long long)((const int*)dstp)[e];
    }

    // segment = col/32 = lane/8 ; all 4 floats of this chunk share one coeff
    float c = __ldg(coeffs + (lane >> 3));

    float4 yv = *reinterpret_cast<const float4*>(y + (size_t)e * D + col);
    float4 xv = __ldg(reinterpret_cast<const float4*>(x + (size_t)s * D + col));

    float4 p;
    p.x = xv.x * yv.x * c;
    p.y = xv.y * yv.y * c;
    p.z = xv.z * yv.z * c;
    p.w = xv.w * yv.w * c;

    float* addr = out + (size_t)d * D + col;
    // Fire-and-forget vector reduction: 1 REDG moves 16B, no return trip.
    asm volatile("red.global.add.v4.f32 [%0], {%1, %2, %3, %4};"
                 :: "l"(addr), "f"(p.x), "f"(p.y), "f"(p.z), "f"(p.w)
                 : "memory");
}

extern "C" void kernel_launch(void* const* d_in, const int* in_sizes, int n_in,
                              void* d_out, int out_size) {
    const float* x      = (const float*)d_in[0];
    const float* y      = (const float*)d_in[1];
    const float* coeffs = (const float*)d_in[2];
    const void*  src    = d_in[3];
    const void*  dst    = d_in[4];
    float* out = (float*)d_out;

    int E = in_sizes[1] / D;                 // 1,000,000 (robust to index dtype)
    long long n_nodes = (long long)(out_size / D);

    // 1) dtype sniff for indices (1 thread, trivial cost)
    detect_idx_kernel<<<1, 1>>>(src, n_nodes);

    // 2) zero the output (poisoned 0xAA by harness)
    int n4 = out_size / 4;
    zero_kernel<<<(n4 + 255) / 256, 256>>>((float4*)d_out, n4);

    // 3) fused gather * y * c -> scatter-add ; one warp per edge
    long long total_threads = (long long)E * 32;
    int blocks = (int)((total_threads + 255) / 256);
    tp_scatter_kernel<<<blocks, 256>>>(x, y, coeffs, src, dst, out, E);
}

// round 3
// speedup vs baseline: 1.3466x; 1.3466x over previous
#include <cuda_runtime.h>
#include <cstdint>

#define D 128
#define EPT 4   // edges per warp per iteration

__device__ int g_idx64;

__global__ void detect_idx_kernel(const void* __restrict__ src, long long n_nodes) {
    const long long* s64 = (const long long*)src;
    bool ok = true;
#pragma unroll
    for (int i = 0; i < 8; i++) {
        long long v = s64[i];
        if (v < 0 || v >= n_nodes) ok = false;
    }
    g_idx64 = ok ? 1 : 0;
}

__global__ void zero_kernel(float4* __restrict__ out, int n4) {
    int i = blockIdx.x * blockDim.x + threadIdx.x;
    if (i < n4) out[i] = make_float4(0.f, 0.f, 0.f, 0.f);
}

__global__ __launch_bounds__(256)
void tp_scatter_kernel(const float* __restrict__ x,
                       const float* __restrict__ y,
                       const float* __restrict__ coeffs,
                       const void* __restrict__ srcp,
                       const void* __restrict__ dstp,
                       float* __restrict__ out,
                       int E)
{
    int gid  = blockIdx.x * blockDim.x + threadIdx.x;
    int warp = gid >> 5;
    int lane = gid & 31;
    int col  = lane << 2;                  // 16B chunk per lane
    int e0   = warp * EPT;
    if (e0 >= E) return;

    const bool i64 = (g_idx64 != 0);       // uniform

    // ---- 1) all index loads up front (independent, broadcast within warp)
    long long s[EPT], d[EPT];
#pragma unroll
    for (int k = 0; k < EPT; k++) {
        int e = e0 + k;
        if (e < E) {
            if (i64) {
                s[k] = ((const long long*)srcp)[e];
                d[k] = ((const long long*)dstp)[e];
            } else {
                s[k] = (long long)((const int*)srcp)[e];
                d[k] = (long long)((const int*)dstp)[e];
            }
        } else { s[k] = 0; d[k] = 0; }
    }

    float c = __ldg(coeffs + (lane >> 3)); // segment = lane/8

    // ---- 2) y loads: streamed once -> .cs (evict-first) so x table + out stay L2-resident
    float4 yv[EPT];
#pragma unroll
    for (int k = 0; k < EPT; k++) {
        int e = e0 + k;
        yv[k] = __ldcs(reinterpret_cast<const float4*>(y + (size_t)min(e, E - 1) * D + col));
    }

    // ---- 3) x gathers: 4 independent L2-hit chains per thread (MLP)
    float4 xv[EPT];
#pragma unroll
    for (int k = 0; k < EPT; k++) {
        xv[k] = __ldg(reinterpret_cast<const float4*>(x + (size_t)s[k] * D + col));
    }

    // ---- 4) fused multiply + vector reduction (fire-and-forget)
#pragma unroll
    for (int k = 0; k < EPT; k++) {
        int e = e0 + k;
        if (e < E) {
            float px = xv[k].x * yv[k].x * c;
            float py = xv[k].y * yv[k].y * c;
            float pz = xv[k].z * yv[k].z * c;
            float pw = xv[k].w * yv[k].w * c;
            float* addr = out + (size_t)d[k] * D + col;
            asm volatile("red.global.add.v4.f32 [%0], {%1, %2, %3, %4};"
                         :: "l"(addr), "f"(px), "f"(py), "f"(pz), "f"(pw)
                         : "memory");
        }
    }
}

extern "C" void kernel_launch(void* const* d_in, const int* in_sizes, int n_in,
                              void* d_out, int out_size) {
    const float* x      = (const float*)d_in[0];
    const float* y      = (const float*)d_in[1];
    const float* coeffs = (const float*)d_in[2];
    const void*  src    = d_in[3];
    const void*  dst    = d_in[4];
    float* out = (float*)d_out;

    int E = in_sizes[1] / D;
    long long n_nodes = (long long)(out_size / D);

    detect_idx_kernel<<<1, 1>>>(src, n_nodes);

    int n4 = out_size / 4;
    zero_kernel<<<(n4 + 255) / 256, 256>>>((float4*)d_out, n4);

    int warps  = (E + EPT - 1) / EPT;              // 250k warps
    long long total_threads = (long long)warps * 32;
    int blocks = (int)((total_threads + 255) / 256);
    tp_scatter_kernel<<<blocks, 256>>>(x, y, coeffs, src, dst, out, E);
}

// round 4
// speedup vs baseline: 1.3578x; 1.0083x over previous
#include <cuda_runtime.h>
#include <cstdint>

#define D 128
#define EPT 4   // edges per warp

__global__ __launch_bounds__(256)
void tp_scatter_kernel(const float* __restrict__ x,
                       const float* __restrict__ y,
                       const float* __restrict__ coeffs,
                       const void* __restrict__ srcp,
                       const void* __restrict__ dstp,
                       float* __restrict__ out,
                       int E, long long n_nodes)
{
    // ---- index dtype detection, once per block (uniform, L2-hit broadcast)
    __shared__ int sh_i64;
    if (threadIdx.x == 0) {
        const long long* s64 = (const long long*)srcp;
        bool ok = true;
#pragma unroll
        for (int i = 0; i < 8; i++) {
            long long v = s64[i];
            if (v < 0 || v >= n_nodes) ok = false;
        }
        sh_i64 = ok ? 1 : 0;
    }
    __syncthreads();
    const bool i64 = (sh_i64 != 0);

    int gid  = blockIdx.x * blockDim.x + threadIdx.x;
    int warp = gid >> 5;
    int lane = gid & 31;
    int col  = lane << 2;                  // 16B chunk per lane
    int e0   = warp * EPT;
    if (e0 >= E) return;

    // ---- 1) index loads up front (independent, broadcast within warp)
    long long s[EPT], d[EPT];
#pragma unroll
    for (int k = 0; k < EPT; k++) {
        int e = e0 + k;
        if (e < E) {
            if (i64) {
                s[k] = ((const long long*)srcp)[e];
                d[k] = ((const long long*)dstp)[e];
            } else {
                s[k] = (long long)((const int*)srcp)[e];
                d[k] = (long long)((const int*)dstp)[e];
            }
        } else { s[k] = 0; d[k] = 0; }
    }

    float c = __ldg(coeffs + (lane >> 3)); // segment = lane/8

    // ---- 2) y: streamed once -> .cs keeps x table + out resident in L2
    float4 yv[EPT];
#pragma unroll
    for (int k = 0; k < EPT; k++) {
        int e = e0 + k;
        yv[k] = __ldcs(reinterpret_cast<const float4*>(y + (size_t)min(e, E - 1) * D + col));
    }

    // ---- 3) x gathers: 4 independent L2-hit chains per thread (MLP)
    float4 xv[EPT];
#pragma unroll
    for (int k = 0; k < EPT; k++) {
        xv[k] = __ldg(reinterpret_cast<const float4*>(x + (size_t)s[k] * D + col));
    }

    // ---- 4) fused multiply + fire-and-forget vector reduction
#pragma unroll
    for (int k = 0; k < EPT; k++) {
        int e = e0 + k;
        if (e < E) {
            float px = xv[k].x * yv[k].x * c;
            float py = xv[k].y * yv[k].y * c;
            float pz = xv[k].z * yv[k].z * c;
            float pw = xv[k].w * yv[k].w * c;
            float* addr = out + (size_t)d[k] * D + col;
            asm volatile("red.global.add.v4.f32 [%0], {%1, %2, %3, %4};"
                         :: "l"(addr), "f"(px), "f"(py), "f"(pz), "f"(pw)
                         : "memory");
        }
    }
}

extern "C" void kernel_launch(void* const* d_in, const int* in_sizes, int n_in,
                              void* d_out, int out_size) {
    const float* x      = (const float*)d_in[0];
    const float* y      = (const float*)d_in[1];
    const float* coeffs = (const float*)d_in[2];
    const void*  src    = d_in[3];
    const void*  dst    = d_in[4];
    float* out = (float*)d_out;

    int E = in_sizes[1] / D;
    long long n_nodes = (long long)(out_size / D);

    // zero the poisoned output via a graph-capturable memset node
    cudaMemsetAsync(d_out, 0, (size_t)out_size * sizeof(float), 0);

    int warps  = (E + EPT - 1) / EPT;              // 250k warps
    long long total_threads = (long long)warps * 32;
    int blocks = (int)((total_threads + 255) / 256);
    tp_scatter_kernel<<<blocks, 256>>>(x, y, coeffs, src, dst, out, E, n_nodes);
}

// round 5
// speedup vs baseline: 1.3763x; 1.0137x over previous
#include <cuda_runtime.h>
#include <cstdint>

#define D 128
#define EPT 4   // edges per warp

__global__ __launch_bounds__(256)
void tp_scatter_kernel(const float* __restrict__ x,
                       const float* __restrict__ y,
                       const float* __restrict__ coeffs,
                       const void* __restrict__ srcp,
                       const void* __restrict__ dstp,
                       float* __restrict__ out,
                       int E, long long n_nodes)
{
    // ---- index dtype detection, once per block (uniform, L2-hit broadcast)
    __shared__ int sh_i64;
    if (threadIdx.x == 0) {
        const long long* s64 = (const long long*)srcp;
        bool ok = true;
#pragma unroll
        for (int i = 0; i < 8; i++) {
            long long v = s64[i];
            if (v < 0 || v >= n_nodes) ok = false;
        }
        sh_i64 = ok ? 1 : 0;
    }
    __syncthreads();
    const bool i64 = (sh_i64 != 0);

    int gid  = blockIdx.x * blockDim.x + threadIdx.x;
    int warp = gid >> 5;
    int lane = gid & 31;
    int col  = lane << 2;                  // 16B chunk per lane
    int e0   = warp * EPT;
    if (e0 >= E) return;

    // L2 policy: keep the x table resident against the streaming y traffic
    unsigned long long pol_last;
    asm volatile("createpolicy.fractional.L2::evict_last.b64 %0, 1.0;"
                 : "=l"(pol_last));

    // ---- 1) index loads up front (independent, broadcast within warp)
    long long s[EPT], d[EPT];
#pragma unroll
    for (int k = 0; k < EPT; k++) {
        int e = e0 + k;
        if (e < E) {
            if (i64) {
                s[k] = ((const long long*)srcp)[e];
                d[k] = ((const long long*)dstp)[e];
            } else {
                s[k] = (long long)((const int*)srcp)[e];
                d[k] = (long long)((const int*)dstp)[e];
            }
        } else { s[k] = 0; d[k] = 0; }
    }

    float c = __ldg(coeffs + (lane >> 3)); // segment = lane/8

    // ---- 2) y: streamed once -> .cs (evict-first) frees L2 for x + out
    float4 yv[EPT];
#pragma unroll
    for (int k = 0; k < EPT; k++) {
        int e = e0 + k;
        yv[k] = __ldcs(reinterpret_cast<const float4*>(y + (size_t)min(e, E - 1) * D + col));
    }

    // ---- 3) x gathers: evict-last policy pins the 51MB table in L2
    float4 xv[EPT];
#pragma unroll
    for (int k = 0; k < EPT; k++) {
        const float* xp = x + (size_t)s[k] * D + col;
        asm volatile("ld.global.nc.L2::cache_hint.v4.f32 {%0,%1,%2,%3}, [%4], %5;"
                     : "=f"(xv[k].x), "=f"(xv[k].y), "=f"(xv[k].z), "=f"(xv[k].w)
                     : "l"(xp), "l"(pol_last));
    }

    // ---- 4) fused multiply + fire-and-forget vector reduction
#pragma unroll
    for (int k = 0; k < EPT; k++) {
        int e = e0 + k;
        if (e < E) {
            float px = xv[k].x * yv[k].x * c;
            float py = xv[k].y * yv[k].y * c;
            float pz = xv[k].z * yv[k].z * c;
            float pw = xv[k].w * yv[k].w * c;
            float* addr = out + (size_t)d[k] * D + col;
            asm volatile("red.global.add.v4.f32 [%0], {%1, %2, %3, %4};"
                         :: "l"(addr), "f"(px), "f"(py), "f"(pz), "f"(pw)
                         : "memory");
        }
    }
}

extern "C" void kernel_launch(void* const* d_in, const int* in_sizes, int n_in,
                              void* d_out, int out_size) {
    const float* x      = (const float*)d_in[0];
    const float* y      = (const float*)d_in[1];
    const float* coeffs = (const float*)d_in[2];
    const void*  src    = d_in[3];
    const void*  dst    = d_in[4];
    float* out = (float*)d_out;

    int E = in_sizes[1] / D;
    long long n_nodes = (long long)(out_size / D);

    // zero the poisoned output via a graph-capturable memset node
    cudaMemsetAsync(d_out, 0, (size_t)out_size * sizeof(float), 0);

    int warps  = (E + EPT - 1) / EPT;              // 250k warps
    long long total_threads = (long long)warps * 32;
    int blocks = (int)((total_threads + 255) / 256);
    tp_scatter_kernel<<<blocks, 256>>>(x, y, coeffs, src, dst, out, E, n_nodes);
}